// round 7
// baseline (speedup 1.0000x reference)
#include <cuda_runtime.h>
#include <cuda_fp16.h>
#include <math.h>
#include <stdint.h>

// ---------------- static problem shape ----------------
#define Bb 16
#define Ss 512
#define Nn 16
#define WD 300
#define ED 64
#define SD 512
#define NK1 364           // WD+ED
#define KP1 384           // padded to 32
#define KP2 576           // SD+ED (Ug row count)
#define Mrows (Bb*Ss)     // 8192
#define NT 2048           // 4 gates * SD, interleaved n = c*4+g
#define NLAYERS 3

// ---------------- scratch (device globals; no allocations) ----------------
__device__ __align__(256) __half g_irep  [(size_t)Mrows*KP1];   // word+edge (no sm)
__device__ __align__(256) __half g_orep  [(size_t)Mrows*KP1];
__device__ __align__(256) __half g_iedgeS[(size_t)Mrows*ED];    // sm * edge_sum
__device__ __align__(256) __half g_oedgeS[(size_t)Mrows*ED];
__device__ __align__(256) __half g_hin   [(size_t)Mrows*SD];
__device__ __align__(256) __half g_hout  [(size_t)Mrows*SD];
__device__ __align__(256) __half g_Win_hi [(size_t)NT*KP1];
__device__ __align__(256) __half g_Win_lo [(size_t)NT*KP1];
__device__ __align__(256) __half g_Wout_hi[(size_t)NT*KP1];
__device__ __align__(256) __half g_Wout_lo[(size_t)NT*KP1];
__device__ __align__(256) __half g_Uin_hi [(size_t)NT*KP2];
__device__ __align__(256) __half g_Uin_lo [(size_t)NT*KP2];
__device__ __align__(256) __half g_Uout_hi[(size_t)NT*KP2];
__device__ __align__(256) __half g_Uout_lo[(size_t)NT*KP2];
__device__ __align__(256) float  g_bias_i[NT];
__device__ __align__(256) float  g_wterms[(size_t)Mrows*NT];
__device__ __align__(256) float  g_cell  [(size_t)Mrows*SD];

// ---------------- helpers ----------------
__device__ __forceinline__ uint32_t smem_u32(const void* p) {
    uint32_t a;
    asm("{ .reg .u64 t; cvta.to.shared.u64 t, %1; cvt.u32.u64 %0, t; }" : "=r"(a) : "l"(p));
    return a;
}
__device__ __forceinline__ void cpasync16(uint32_t dst, const void* src) {
    asm volatile("cp.async.ca.shared.global [%0], [%1], 16;" :: "r"(dst), "l"(src));
}
#define CP_COMMIT() asm volatile("cp.async.commit_group;" ::: "memory")
#define CP_WAIT(n)  asm volatile("cp.async.wait_group %0;" :: "n"(n) : "memory")

__device__ __forceinline__ void ldm_x4(uint32_t* r, uint32_t addr) {
    asm volatile("ldmatrix.sync.aligned.m8n8.x4.shared.b16 {%0,%1,%2,%3}, [%4];"
        : "=r"(r[0]), "=r"(r[1]), "=r"(r[2]), "=r"(r[3]) : "r"(addr));
}
__device__ __forceinline__ void mma16816(float* d, const uint32_t* a, uint32_t b0, uint32_t b1) {
    asm volatile("mma.sync.aligned.m16n8k16.row.col.f32.f16.f16.f32 "
        "{%0,%1,%2,%3}, {%4,%5,%6,%7}, {%8,%9}, {%0,%1,%2,%3};"
        : "+f"(d[0]), "+f"(d[1]), "+f"(d[2]), "+f"(d[3])
        : "r"(a[0]), "r"(a[1]), "r"(a[2]), "r"(a[3]), "r"(b0), "r"(b1));
}
__device__ __forceinline__ void split2h(float v, __half& hi, __half& lo) {
    hi = __float2half_rn(v);
    lo = __float2half_rn(v - __half2float(hi));
}
__device__ __forceinline__ float sigf(float x) { return 1.f / (1.f + __expf(-x)); }

// ---------------- weight transpose + split: W[g][k][c] -> Bt[(c*4+g)][k] fp16 hi/lo ----------------
template<int KSRC, int KPAD>
__global__ void conv_w_kernel(const float* __restrict__ W,
                              __half* __restrict__ dhi,
                              __half* __restrict__ dlo)
{
    __shared__ float t[32][33];
    int g = blockIdx.z, k0 = blockIdx.x * 32, c0 = blockIdx.y * 32;
    int tx = threadIdx.x, ty = threadIdx.y;   // 32 x 8
    #pragma unroll
    for (int i = 0; i < 4; i++) {
        int k = k0 + ty + i * 8;
        float v = (k < KSRC) ? W[((size_t)g * KSRC + k) * SD + c0 + tx] : 0.f;
        t[ty + i * 8][tx] = v;
    }
    __syncthreads();
    #pragma unroll
    for (int i = 0; i < 4; i++) {
        int c = ty + i * 8;
        int n = (c0 + c) * 4 + g;
        float v = t[tx][c];
        __half hi, lo; split2h(v, hi, lo);
        dhi[(size_t)n * KPAD + k0 + tx] = hi;
        dlo[(size_t)n * KPAD + k0 + tx] = lo;
    }
}

__global__ void bias_kernel(const float* __restrict__ b) {
    int n = blockIdx.x * 256 + threadIdx.x;
    if (n < NT) g_bias_i[n] = b[(n & 3) * SD + (n >> 2)];
}

// ---------------- static neighbor word+edge sums ----------------
__global__ void prep_rep_kernel(const float* __restrict__ word,
                                const float* __restrict__ edge_emb,
                                const float* __restrict__ seq_mask,
                                const int* __restrict__ in_idx,
                                const int* __restrict__ in_edges,
                                const float* __restrict__ in_mask,
                                const int* __restrict__ out_idx,
                                const int* __restrict__ out_edges,
                                const float* __restrict__ out_mask)
{
    int node = blockIdx.x;
    int b = node / Ss;
    float sm = seq_mask[node];
    __shared__ int   s_idx [2][Nn];
    __shared__ int   s_edge[2][Nn];
    __shared__ float s_msk [2][Nn];
    int tid = threadIdx.x;
    if (tid < Nn) {
        s_idx [0][tid] = in_idx  [(size_t)node*Nn + tid];
        s_edge[0][tid] = in_edges[(size_t)node*Nn + tid];
        s_msk [0][tid] = in_mask [(size_t)node*Nn + tid];
        s_idx [1][tid] = out_idx  [(size_t)node*Nn + tid];
        s_edge[1][tid] = out_edges[(size_t)node*Nn + tid];
        s_msk [1][tid] = out_mask [(size_t)node*Nn + tid];
    }
    __syncthreads();

    #pragma unroll
    for (int dir = 0; dir < 2; dir++) {
        __half* rep = dir ? g_orep : g_irep;
        __half* edS = dir ? g_oedgeS : g_iedgeS;
        for (int d = tid; d < WD; d += blockDim.x) {
            float acc = 0.f;
            #pragma unroll
            for (int n = 0; n < Nn; n++)
                acc += s_msk[dir][n] * word[((size_t)b*Ss + s_idx[dir][n])*WD + d];
            rep[(size_t)node*KP1 + d] = __float2half_rn(acc);
        }
        for (int d = tid; d < ED; d += blockDim.x) {
            float acc = 0.f;
            #pragma unroll
            for (int n = 0; n < Nn; n++)
                acc += s_msk[dir][n] * edge_emb[(size_t)s_edge[dir][n]*ED + d];
            rep[(size_t)node*KP1 + WD + d] = __float2half_rn(acc);
            edS[(size_t)node*ED + d] = __float2half_rn(acc * sm);
        }
        for (int d = NK1 + tid; d < KP1; d += blockDim.x)
            rep[(size_t)node*KP1 + d] = __float2half_rn(0.f);
    }
}

// ---------------- per-layer hidden gather (float4, single fp16 out) ----------------
__global__ void gather_h_kernel(const float* __restrict__ H,
                                const float* __restrict__ seq_mask,
                                const int* __restrict__ in_idx,
                                const float* __restrict__ in_mask,
                                const int* __restrict__ out_idx,
                                const float* __restrict__ out_mask)
{
    int node = blockIdx.x;
    int b = node / Ss;
    float sm = seq_mask[node];
    __shared__ int   s_idx[2][Nn];
    __shared__ float s_msk[2][Nn];
    int tid = threadIdx.x;   // 128 threads, each owns 4 dims
    if (tid < Nn) {
        s_idx[0][tid] = in_idx [(size_t)node*Nn + tid];
        s_msk[0][tid] = in_mask[(size_t)node*Nn + tid];
        s_idx[1][tid] = out_idx [(size_t)node*Nn + tid];
        s_msk[1][tid] = out_mask[(size_t)node*Nn + tid];
    }
    __syncthreads();

    const float4* Hb4 = reinterpret_cast<const float4*>(H + (size_t)b*Ss*SD);
    float4 ai = make_float4(0,0,0,0), ao = make_float4(0,0,0,0);
    #pragma unroll
    for (int n = 0; n < Nn; n++) {
        float m0 = s_msk[0][n];
        float4 v = Hb4[(size_t)s_idx[0][n]*(SD/4) + tid];
        ai.x += m0*v.x; ai.y += m0*v.y; ai.z += m0*v.z; ai.w += m0*v.w;
        float m1 = s_msk[1][n];
        float4 w = Hb4[(size_t)s_idx[1][n]*(SD/4) + tid];
        ao.x += m1*w.x; ao.y += m1*w.y; ao.z += m1*w.z; ao.w += m1*w.w;
    }
    __half2* pin  = reinterpret_cast<__half2*>(g_hin  + (size_t)node*SD) + tid*2;
    __half2* pout = reinterpret_cast<__half2*>(g_hout + (size_t)node*SD) + tid*2;
    pin[0]  = __floats2half2_rn(ai.x*sm, ai.y*sm);
    pin[1]  = __floats2half2_rn(ai.z*sm, ai.w*sm);
    pout[0] = __floats2half2_rn(ao.x*sm, ao.y*sm);
    pout[1] = __floats2half2_rn(ao.z*sm, ao.w*sm);
}

// ---------------- segmented fp16 2-product GEMM, tile 128x256, 512 threads ----------------
#define ROWP 80
#define A_MATB 10240        // 128 rows * 80B
#define B_MATB 20480        // 256 rows * 80B
#define STAGEB (A_MATB + 2*B_MATB)   // 51200
#define SMEM_TOT (2*STAGEB)          // 102400

struct Seg { const __half* A; const __half* Bh; const __half* Bl; int apitch, bpitch, nchunk; };
struct SegList { Seg s[4]; int nseg; };

__device__ __forceinline__ void chunk_src(const SegList& L, int idx, int row0, int n0,
    const __half*& A, const __half*& Bh, const __half*& Bl, int& ap, int& bp)
{
    #pragma unroll
    for (int s = 0; s < 4; s++) {
        if (s < L.nseg) {
            int n = L.s[s].nchunk;
            if (idx < n) {
                int k0 = idx * 32;
                ap = L.s[s].apitch; bp = L.s[s].bpitch;
                A  = L.s[s].A  + (size_t)row0 * ap + k0;
                Bh = L.s[s].Bh + (size_t)n0  * bp + k0;
                Bl = L.s[s].Bl + (size_t)n0  * bp + k0;
                return;
            }
            idx -= n;
        }
    }
}

__device__ __forceinline__ void load_chunk(uint32_t st,
    const __half* __restrict__ A, int ap,
    const __half* __restrict__ Bh, const __half* __restrict__ Bl, int bp, int tid)
{
    {   // A: 128 rows x 4 segs = 512 items
        int row = tid >> 2, seg = tid & 3;
        cpasync16(st + (uint32_t)(row * ROWP + seg * 16),
                  (const char*)(A + (size_t)row * ap) + seg * 16);
    }
    #pragma unroll
    for (int i = 0; i < 2; i++) {  // B: 256 rows x 4 segs = 1024 items per matrix
        int idx = tid + i * 512;
        int row = idx >> 2, seg = idx & 3;
        uint32_t doff = (uint32_t)(row * ROWP + seg * 16);
        cpasync16(st + A_MATB          + doff, (const char*)(Bh + (size_t)row * bp) + seg * 16);
        cpasync16(st + A_MATB + B_MATB + doff, (const char*)(Bl + (size_t)row * bp) + seg * 16);
    }
}

// MODE 0: Cout[row][NT] = D + bias_i
// MODE 1: gates = D + w_terms -> LSTM -> Cout = h (SD layout), cell updated
// MODE 2: MODE 1 + finalH/finalC
template<int MODE>
__global__ __launch_bounds__(512, 1)
void mma_gemm(SegList L, int NC,
              const float* __restrict__ wob,
              const float* __restrict__ seq_mask,
              float* __restrict__ Cout,
              float* __restrict__ cell,
              float* __restrict__ finalH, float* __restrict__ finalC,
              int first)
{
    extern __shared__ char smem[];
    uint32_t sb = smem_u32(smem);
    int tid = threadIdx.x;
    int wid = tid >> 5, lane = tid & 31;
    int wm = wid >> 3, wn = wid & 7;       // warp 2x8: each 64 rows x 32 cols
    int row0 = blockIdx.x * 128;
    int n0   = blockIdx.y * 256;

    float acc[4][4][4];
    #pragma unroll
    for (int a = 0; a < 4; a++)
        #pragma unroll
        for (int b = 0; b < 4; b++)
            #pragma unroll
            for (int c = 0; c < 4; c++) acc[a][b][c] = 0.f;

    uint32_t aAddr = (uint32_t)((wm * 64 + (lane & 15)) * ROWP + ((lane >> 4) << 4));
    uint32_t bRow  = (uint32_t)(wn * 32 + (lane & 7) + ((lane >> 4) << 3));
    uint32_t bAddr = bRow * ROWP + (((lane >> 3) & 1) << 4);

    // prologue: chunk 0 -> stage 0
    {
        const __half *A, *Bh, *Bl; int ap, bp;
        chunk_src(L, 0, row0, n0, A, Bh, Bl, ap, bp);
        load_chunk(sb, A, ap, Bh, Bl, bp, tid);
        CP_COMMIT();
    }

    for (int ci = 0; ci < NC; ci++) {
        if (ci + 1 < NC) {
            const __half *A, *Bh, *Bl; int ap, bp;
            chunk_src(L, ci + 1, row0, n0, A, Bh, Bl, ap, bp);
            load_chunk(sb + (uint32_t)((ci + 1) & 1) * STAGEB, A, ap, Bh, Bl, bp, tid);
        }
        CP_COMMIT();
        CP_WAIT(1);
        __syncthreads();

        uint32_t st = sb + (uint32_t)(ci & 1) * STAGEB;
        #pragma unroll
        for (int k16 = 0; k16 < 2; k16++) {
            uint32_t ko = (uint32_t)(k16 * 32);
            uint32_t aH[4][4], bH[2][4], bL[2][4];
            #pragma unroll
            for (int tm = 0; tm < 4; tm++)
                ldm_x4(aH[tm], st + aAddr + (uint32_t)(tm*16*ROWP) + ko);
            #pragma unroll
            for (int p = 0; p < 2; p++) {
                ldm_x4(bH[p], st + A_MATB          + bAddr + (uint32_t)(p*16*ROWP) + ko);
                ldm_x4(bL[p], st + A_MATB + B_MATB + bAddr + (uint32_t)(p*16*ROWP) + ko);
            }
            #pragma unroll
            for (int tm = 0; tm < 4; tm++) {
                #pragma unroll
                for (int tn = 0; tn < 4; tn++) {
                    int p = tn >> 1, h = (tn & 1) * 2;
                    mma16816(acc[tm][tn], aH[tm], bH[p][h], bH[p][h+1]);
                    mma16816(acc[tm][tn], aH[tm], bL[p][h], bL[p][h+1]);
                }
            }
        }
        __syncthreads();
        }

    // ---------------- epilogue: two 128-col halves staged through smem ----------------
    float* sC = (float*)smem;
    #pragma unroll
    for (int half = 0; half < 2; half++) {
        __syncthreads();
        if ((wn >> 2) == half) {
            int wnl = wn & 3;
            #pragma unroll
            for (int tm = 0; tm < 4; tm++) {
                #pragma unroll
                for (int tn = 0; tn < 4; tn++) {
                    #pragma unroll
                    for (int r = 0; r < 4; r++) {
                        int row = wm*64 + tm*16 + (lane >> 2) + ((r >> 1) << 3);
                        int nn  = wnl*32 + tn*8 + (lane & 3)*2 + (r & 1);
                        sC[row * 136 + nn] = acc[tm][tn][r];
                    }
                }
            }
        }
        __syncthreads();

        int nb = n0 + half * 128;
        if (MODE == 0) {
            #pragma unroll
            for (int j = 0; j < 8; j++) {
                int item = j * 512 + tid;
                int row = item >> 5, q = item & 31;
                float4 v  = *reinterpret_cast<float4*>(sC + row * 136 + q * 4);
                float4 bv = *reinterpret_cast<const float4*>(wob + nb + q * 4);
                v.x += bv.x; v.y += bv.y; v.z += bv.z; v.w += bv.w;
                *reinterpret_cast<float4*>(Cout + (size_t)(row0 + row) * NT + nb + q * 4) = v;
            }
        } else {
            int c0g = nb >> 2;
            #pragma unroll
            for (int j = 0; j < 8; j++) {
                int item = j * 512 + tid;
                int row = item >> 5, c = item & 31;
                int grow = row0 + row;
                int cg = c0g + c;
                float4 g  = *reinterpret_cast<float4*>(sC + row * 136 + c * 4);
                float4 wv = *reinterpret_cast<const float4*>(wob + (size_t)grow * NT + nb + c * 4);
                float gi = g.x + wv.x, gf = g.y + wv.y, go = g.z + wv.z, gc = g.w + wv.w;
                float ig = sigf(gi), fg = sigf(gf), og = sigf(go), ci = tanhf(gc);
                float sm = seq_mask[grow];
                float cp = first ? 0.f : cell[(size_t)grow * SD + cg];
                float tc = fg * cp + ig * ci;
                float th = og * tanhf(tc);
                float cv = tc * sm, hv = th * sm;
                cell[(size_t)grow * SD + cg] = cv;
                Cout[(size_t)grow * SD + cg] = hv;
                if (MODE == 2) {
                    finalH[(size_t)grow * SD + cg] = hv;
                    finalC[(size_t)grow * SD + cg] = cv;
                }
            }
        }
    }
}

// ---------------- launch ----------------
extern "C" void kernel_launch(void* const* d_in, const int* in_sizes, int n_in,
                              void* d_out, int out_size)
{
    const float* word     = (const float*)d_in[0];
    const float* sent     = (const float*)d_in[1];
    const float* seq_mask = (const float*)d_in[2];
    const float* in_mask  = (const float*)d_in[3];
    const float* out_mask = (const float*)d_in[4];
    const float* edge_emb = (const float*)d_in[5];
    const float* Wg_in    = (const float*)d_in[6];
    const float* Ug_in    = (const float*)d_in[7];
    const float* Wg_out   = (const float*)d_in[8];
    const float* Ug_out   = (const float*)d_in[9];
    const float* bvec     = (const float*)d_in[10];
    const int*   in_idx   = (const int*)d_in[11];
    const int*   in_edges = (const int*)d_in[12];
    const int*   out_idx  = (const int*)d_in[13];
    const int*   out_edges= (const int*)d_in[14];
    float* out = (float*)d_out;

    cudaFuncSetAttribute(mma_gemm<0>, cudaFuncAttributeMaxDynamicSharedMemorySize, SMEM_TOT);
    cudaFuncSetAttribute(mma_gemm<1>, cudaFuncAttributeMaxDynamicSharedMemorySize, SMEM_TOT);
    cudaFuncSetAttribute(mma_gemm<2>, cudaFuncAttributeMaxDynamicSharedMemorySize, SMEM_TOT);

    __half *p_irep,*p_orep,*p_iedS,*p_oedS,*p_hin,*p_hout;
    __half *p_Winh,*p_Winl,*p_Wouth,*p_Woutl,*p_Uinh,*p_Uinl,*p_Uouth,*p_Uoutl;
    float *p_bias,*p_wt,*p_cell;
    cudaGetSymbolAddress((void**)&p_irep,  g_irep);
    cudaGetSymbolAddress((void**)&p_orep,  g_orep);
    cudaGetSymbolAddress((void**)&p_iedS,  g_iedgeS);
    cudaGetSymbolAddress((void**)&p_oedS,  g_oedgeS);
    cudaGetSymbolAddress((void**)&p_hin,   g_hin);
    cudaGetSymbolAddress((void**)&p_hout,  g_hout);
    cudaGetSymbolAddress((void**)&p_Winh,  g_Win_hi);
    cudaGetSymbolAddress((void**)&p_Winl,  g_Win_lo);
    cudaGetSymbolAddress((void**)&p_Wouth, g_Wout_hi);
    cudaGetSymbolAddress((void**)&p_Woutl, g_Wout_lo);
    cudaGetSymbolAddress((void**)&p_Uinh,  g_Uin_hi);
    cudaGetSymbolAddress((void**)&p_Uinl,  g_Uin_lo);
    cudaGetSymbolAddress((void**)&p_Uouth, g_Uout_hi);
    cudaGetSymbolAddress((void**)&p_Uoutl, g_Uout_lo);
    cudaGetSymbolAddress((void**)&p_bias,  g_bias_i);
    cudaGetSymbolAddress((void**)&p_wt,    g_wterms);
    cudaGetSymbolAddress((void**)&p_cell,  g_cell);

    const size_t GS = (size_t)Mrows * SD;
    dim3 tb(32, 8);

    // 1) weight transpose + split
    conv_w_kernel<NK1,KP1><<<dim3(KP1/32, SD/32, 4), tb>>>(Wg_in,  p_Winh,  p_Winl);
    conv_w_kernel<NK1,KP1><<<dim3(KP1/32, SD/32, 4), tb>>>(Wg_out, p_Wouth, p_Woutl);
    conv_w_kernel<KP2,KP2><<<dim3(KP2/32, SD/32, 4), tb>>>(Ug_in,  p_Uinh,  p_Uinl);
    conv_w_kernel<KP2,KP2><<<dim3(KP2/32, SD/32, 4), tb>>>(Ug_out, p_Uouth, p_Uoutl);
    bias_kernel<<<NT/256, 256>>>(bvec);

    // 2) static neighbor sums
    prep_rep_kernel<<<Mrows, 128>>>(word, edge_emb, seq_mask,
                                    in_idx, in_edges, in_mask,
                                    out_idx, out_edges, out_mask);

    // 3) w_terms GEMM (incl. folded static edge terms of U-GEMMs)
    {
        SegList L;
        L.s[0] = { p_irep, p_Winh,        p_Winl,        KP1, KP1, KP1/32 };
        L.s[1] = { p_orep, p_Wouth,       p_Woutl,       KP1, KP1, KP1/32 };
        L.s[2] = { p_iedS, p_Uinh  + SD,  p_Uinl  + SD,  ED,  KP2, ED/32  };
        L.s[3] = { p_oedS, p_Uouth + SD,  p_Uoutl + SD,  ED,  KP2, ED/32  };
        L.nseg = 4;
        int NC = 2 * (KP1/32) + 2 * (ED/32);   // 28
        dim3 grid(Mrows/128, NT/256);
        mma_gemm<0><<<grid, 512, SMEM_TOT>>>(L, NC, p_bias, seq_mask,
                                             p_wt, nullptr, nullptr, nullptr, 0);
    }

    // 4) layers
    for (int l = 0; l < NLAYERS; l++) {
        const float* H = (l == 0) ? sent : (out + (size_t)(l-1)*GS);
        gather_h_kernel<<<Mrows, 128>>>(H, seq_mask, in_idx, in_mask, out_idx, out_mask);

        SegList L;
        L.s[0] = { p_hin,  p_Uinh,  p_Uinl,  SD, KP2, SD/32 };
        L.s[1] = { p_hout, p_Uouth, p_Uoutl, SD, KP2, SD/32 };
        L.s[2] = L.s[0]; L.s[3] = L.s[0];
        L.nseg = 2;
        int NC = 2 * (SD/32);   // 32
        dim3 grid(Mrows/128, NT/256);
        float* repL = out + (size_t)l*GS;
        if (l < NLAYERS-1) {
            mma_gemm<1><<<grid, 512, SMEM_TOT>>>(L, NC, p_wt, seq_mask,
                                                 repL, p_cell, nullptr, nullptr, (l == 0) ? 1 : 0);
        } else {
            mma_gemm<2><<<grid, 512, SMEM_TOT>>>(L, NC, p_wt, seq_mask,
                                                 repL, p_cell, out + 3*GS, out + 4*GS, 0);
        }
    }
}

// round 9
// speedup vs baseline: 1.2599x; 1.2599x over previous
#include <cuda_runtime.h>
#include <cuda_fp16.h>
#include <math.h>
#include <stdint.h>

// ---------------- static problem shape ----------------
#define Bb 16
#define Ss 512
#define Nn 16
#define WD 300
#define ED 64
#define SD 512
#define NK1 364           // WD+ED
#define KP1 384           // padded to 32
#define KP2 576           // SD+ED (Ug row count)
#define Mrows (Bb*Ss)     // 8192
#define NT 2048           // 4 gates * SD, interleaved n = c*4+g
#define NLAYERS 3

// ---------------- scratch (device globals; no allocations) ----------------
__device__ __align__(256) __half g_irep  [(size_t)Mrows*KP1];   // word+edge (no sm)
__device__ __align__(256) __half g_orep  [(size_t)Mrows*KP1];
__device__ __align__(256) __half g_iedgeS[(size_t)Mrows*ED];    // sm * edge_sum
__device__ __align__(256) __half g_oedgeS[(size_t)Mrows*ED];
__device__ __align__(256) __half g_hin   [(size_t)Mrows*SD];
__device__ __align__(256) __half g_hout  [(size_t)Mrows*SD];
__device__ __align__(256) __half g_Win_hi [(size_t)NT*KP1];
__device__ __align__(256) __half g_Win_lo [(size_t)NT*KP1];
__device__ __align__(256) __half g_Wout_hi[(size_t)NT*KP1];
__device__ __align__(256) __half g_Wout_lo[(size_t)NT*KP1];
__device__ __align__(256) __half g_Uin_hi [(size_t)NT*KP2];
__device__ __align__(256) __half g_Uin_lo [(size_t)NT*KP2];
__device__ __align__(256) __half g_Uout_hi[(size_t)NT*KP2];
__device__ __align__(256) __half g_Uout_lo[(size_t)NT*KP2];
__device__ __align__(256) float  g_bias_i[NT];
__device__ __align__(256) float  g_wterms[(size_t)Mrows*NT];
__device__ __align__(256) float  g_cell  [(size_t)Mrows*SD];

// ---------------- helpers ----------------
__device__ __forceinline__ uint32_t smem_u32(const void* p) {
    uint32_t a;
    asm("{ .reg .u64 t; cvta.to.shared.u64 t, %1; cvt.u32.u64 %0, t; }" : "=r"(a) : "l"(p));
    return a;
}
__device__ __forceinline__ void cpasync16(uint32_t dst, const void* src) {
    asm volatile("cp.async.ca.shared.global [%0], [%1], 16;" :: "r"(dst), "l"(src));
}
#define CP_COMMIT() asm volatile("cp.async.commit_group;" ::: "memory")
#define CP_WAIT(n)  asm volatile("cp.async.wait_group %0;" :: "n"(n) : "memory")

__device__ __forceinline__ void ldm_x4(uint32_t* r, uint32_t addr) {
    asm volatile("ldmatrix.sync.aligned.m8n8.x4.shared.b16 {%0,%1,%2,%3}, [%4];"
        : "=r"(r[0]), "=r"(r[1]), "=r"(r[2]), "=r"(r[3]) : "r"(addr));
}
__device__ __forceinline__ void mma16816(float* d, const uint32_t* a, uint32_t b0, uint32_t b1) {
    asm volatile("mma.sync.aligned.m16n8k16.row.col.f32.f16.f16.f32 "
        "{%0,%1,%2,%3}, {%4,%5,%6,%7}, {%8,%9}, {%0,%1,%2,%3};"
        : "+f"(d[0]), "+f"(d[1]), "+f"(d[2]), "+f"(d[3])
        : "r"(a[0]), "r"(a[1]), "r"(a[2]), "r"(a[3]), "r"(b0), "r"(b1));
}
__device__ __forceinline__ void split2h(float v, __half& hi, __half& lo) {
    hi = __float2half_rn(v);
    lo = __float2half_rn(v - __half2float(hi));
}
__device__ __forceinline__ float sigf(float x) { return 1.f / (1.f + __expf(-x)); }

// ---------------- weight transpose + split: W[g][k][c] -> Bt[(c*4+g)][k] fp16 hi/lo ----------------
template<int KSRC, int KPAD>
__global__ void conv_w_kernel(const float* __restrict__ W,
                              __half* __restrict__ dhi,
                              __half* __restrict__ dlo)
{
    __shared__ float t[32][33];
    int g = blockIdx.z, k0 = blockIdx.x * 32, c0 = blockIdx.y * 32;
    int tx = threadIdx.x, ty = threadIdx.y;   // 32 x 8
    #pragma unroll
    for (int i = 0; i < 4; i++) {
        int k = k0 + ty + i * 8;
        float v = (k < KSRC) ? W[((size_t)g * KSRC + k) * SD + c0 + tx] : 0.f;
        t[ty + i * 8][tx] = v;
    }
    __syncthreads();
    #pragma unroll
    for (int i = 0; i < 4; i++) {
        int c = ty + i * 8;
        int n = (c0 + c) * 4 + g;
        float v = t[tx][c];
        __half hi, lo; split2h(v, hi, lo);
        dhi[(size_t)n * KPAD + k0 + tx] = hi;
        dlo[(size_t)n * KPAD + k0 + tx] = lo;
    }
}

__global__ void bias_kernel(const float* __restrict__ b) {
    int n = blockIdx.x * 256 + threadIdx.x;
    if (n < NT) g_bias_i[n] = b[(n & 3) * SD + (n >> 2)];
}

// ---------------- static neighbor word+edge sums ----------------
__global__ void prep_rep_kernel(const float* __restrict__ word,
                                const float* __restrict__ edge_emb,
                                const float* __restrict__ seq_mask,
                                const int* __restrict__ in_idx,
                                const int* __restrict__ in_edges,
                                const float* __restrict__ in_mask,
                                const int* __restrict__ out_idx,
                                const int* __restrict__ out_edges,
                                const float* __restrict__ out_mask)
{
    int node = blockIdx.x;
    int b = node / Ss;
    float sm = seq_mask[node];
    __shared__ int   s_idx [2][Nn];
    __shared__ int   s_edge[2][Nn];
    __shared__ float s_msk [2][Nn];
    int tid = threadIdx.x;
    if (tid < Nn) {
        s_idx [0][tid] = in_idx  [(size_t)node*Nn + tid];
        s_edge[0][tid] = in_edges[(size_t)node*Nn + tid];
        s_msk [0][tid] = in_mask [(size_t)node*Nn + tid];
        s_idx [1][tid] = out_idx  [(size_t)node*Nn + tid];
        s_edge[1][tid] = out_edges[(size_t)node*Nn + tid];
        s_msk [1][tid] = out_mask [(size_t)node*Nn + tid];
    }
    __syncthreads();

    #pragma unroll
    for (int dir = 0; dir < 2; dir++) {
        __half* rep = dir ? g_orep : g_irep;
        __half* edS = dir ? g_oedgeS : g_iedgeS;
        for (int d = tid; d < WD; d += blockDim.x) {
            float acc = 0.f;
            #pragma unroll
            for (int n = 0; n < Nn; n++)
                acc += s_msk[dir][n] * word[((size_t)b*Ss + s_idx[dir][n])*WD + d];
            rep[(size_t)node*KP1 + d] = __float2half_rn(acc);
        }
        for (int d = tid; d < ED; d += blockDim.x) {
            float acc = 0.f;
            #pragma unroll
            for (int n = 0; n < Nn; n++)
                acc += s_msk[dir][n] * edge_emb[(size_t)s_edge[dir][n]*ED + d];
            rep[(size_t)node*KP1 + WD + d] = __float2half_rn(acc);
            edS[(size_t)node*ED + d] = __float2half_rn(acc * sm);
        }
        for (int d = NK1 + tid; d < KP1; d += blockDim.x)
            rep[(size_t)node*KP1 + d] = __float2half_rn(0.f);
    }
}

// ---------------- per-layer hidden gather (float4, single fp16 out) ----------------
__global__ void gather_h_kernel(const float* __restrict__ H,
                                const float* __restrict__ seq_mask,
                                const int* __restrict__ in_idx,
                                const float* __restrict__ in_mask,
                                const int* __restrict__ out_idx,
                                const float* __restrict__ out_mask)
{
    int node = blockIdx.x;
    int b = node / Ss;
    float sm = seq_mask[node];
    __shared__ int   s_idx[2][Nn];
    __shared__ float s_msk[2][Nn];
    int tid = threadIdx.x;   // 128 threads, each owns 4 dims
    if (tid < Nn) {
        s_idx[0][tid] = in_idx [(size_t)node*Nn + tid];
        s_msk[0][tid] = in_mask[(size_t)node*Nn + tid];
        s_idx[1][tid] = out_idx [(size_t)node*Nn + tid];
        s_msk[1][tid] = out_mask[(size_t)node*Nn + tid];
    }
    __syncthreads();

    const float4* Hb4 = reinterpret_cast<const float4*>(H + (size_t)b*Ss*SD);
    float4 ai = make_float4(0,0,0,0), ao = make_float4(0,0,0,0);
    #pragma unroll
    for (int n = 0; n < Nn; n++) {
        float m0 = s_msk[0][n];
        float4 v = Hb4[(size_t)s_idx[0][n]*(SD/4) + tid];
        ai.x += m0*v.x; ai.y += m0*v.y; ai.z += m0*v.z; ai.w += m0*v.w;
        float m1 = s_msk[1][n];
        float4 w = Hb4[(size_t)s_idx[1][n]*(SD/4) + tid];
        ao.x += m1*w.x; ao.y += m1*w.y; ao.z += m1*w.z; ao.w += m1*w.w;
    }
    __half2* pin  = reinterpret_cast<__half2*>(g_hin  + (size_t)node*SD) + tid*2;
    __half2* pout = reinterpret_cast<__half2*>(g_hout + (size_t)node*SD) + tid*2;
    pin[0]  = __floats2half2_rn(ai.x*sm, ai.y*sm);
    pin[1]  = __floats2half2_rn(ai.z*sm, ai.w*sm);
    pout[0] = __floats2half2_rn(ao.x*sm, ao.y*sm);
    pout[1] = __floats2half2_rn(ao.z*sm, ao.w*sm);
}

// ---------------- segmented fp16 2-product GEMM, tile 128x128, 2 CTAs/SM ----------------
#define ROWP 80
#define MATB 10240          // 128 rows * 80B
#define STAGEB (3*MATB)     // A, Bh, Bl = 30720
#define NSTAGE 2
#define SMEM_TOT (NSTAGE*STAGEB)   // 61440 -> 2 CTAs/SM

struct Seg { const __half* A; const __half* Bh; const __half* Bl; int apitch, bpitch, nchunk; };
struct SegList { Seg s[4]; int nseg; };

__device__ __forceinline__ void chunk_src(const SegList& L, int idx, int row0, int n0,
    const __half*& A, const __half*& Bh, const __half*& Bl, int& ap, int& bp)
{
    #pragma unroll
    for (int s = 0; s < 4; s++) {
        if (s < L.nseg) {
            int n = L.s[s].nchunk;
            if (idx < n) {
                int k0 = idx * 32;
                ap = L.s[s].apitch; bp = L.s[s].bpitch;
                A  = L.s[s].A  + (size_t)row0 * ap + k0;
                Bh = L.s[s].Bh + (size_t)n0  * bp + k0;
                Bl = L.s[s].Bl + (size_t)n0  * bp + k0;
                return;
            }
            idx -= n;
        }
    }
}

__device__ __forceinline__ void load_chunk(uint32_t st,
    const __half* __restrict__ A, int ap,
    const __half* __restrict__ Bh, const __half* __restrict__ Bl, int bp, int tid)
{
    #pragma unroll
    for (int i = 0; i < 2; i++) {
        int idx = tid + i * 256;
        int row = idx >> 2, seg = idx & 3;
        uint32_t doff = (uint32_t)(row * ROWP + seg * 16);
        cpasync16(st + 0*MATB + doff, (const char*)(A  + (size_t)row * ap) + seg * 16);
        cpasync16(st + 1*MATB + doff, (const char*)(Bh + (size_t)row * bp) + seg * 16);
        cpasync16(st + 2*MATB + doff, (const char*)(Bl + (size_t)row * bp) + seg * 16);
    }
}

// MODE 0: Cout[row][NT] = D + bias_i
// MODE 1: gates = D + w_terms -> LSTM -> Cout = h (SD layout), cell updated
// MODE 2: MODE 1 + finalH/finalC
template<int MODE>
__global__ __launch_bounds__(256, 2)
void mma_gemm(SegList L, int NC,
              const float* __restrict__ wob,
              const float* __restrict__ seq_mask,
              float* __restrict__ Cout,
              float* __restrict__ cell,
              float* __restrict__ finalH, float* __restrict__ finalC,
              int first)
{
    extern __shared__ char smem[];
    uint32_t sb = smem_u32(smem);
    int tid = threadIdx.x;
    int wid = tid >> 5, lane = tid & 31;
    int wm = wid >> 2, wn = wid & 3;       // warp 2x4: 64 rows x 32 cols
    int row0 = blockIdx.x * 128;
    int n0   = blockIdx.y * 128;

    float acc[4][4][4];
    #pragma unroll
    for (int a = 0; a < 4; a++)
        #pragma unroll
        for (int b = 0; b < 4; b++)
            #pragma unroll
            for (int c = 0; c < 4; c++) acc[a][b][c] = 0.f;

    uint32_t aAddr = (uint32_t)((wm * 64 + (lane & 15)) * ROWP + ((lane >> 4) << 4));
    uint32_t bRow  = (uint32_t)(wn * 32 + (lane & 7) + ((lane >> 4) << 3));
    uint32_t bAddr = bRow * ROWP + (((lane >> 3) & 1) << 4);

    // prologue: chunk 0 -> stage 0
    {
        const __half *A, *Bh, *Bl; int ap, bp;
        chunk_src(L, 0, row0, n0, A, Bh, Bl, ap, bp);
        load_chunk(sb, A, ap, Bh, Bl, bp, tid);
        CP_COMMIT();
    }

    for (int ci = 0; ci < NC; ci++) {
        if (ci + 1 < NC) {
            const __half *A, *Bh, *Bl; int ap, bp;
            chunk_src(L, ci + 1, row0, n0, A, Bh, Bl, ap, bp);
            load_chunk(sb + (uint32_t)((ci + 1) & 1) * STAGEB, A, ap, Bh, Bl, bp, tid);
        }
        CP_COMMIT();
        CP_WAIT(1);
        __syncthreads();

        uint32_t st = sb + (uint32_t)(ci & 1) * STAGEB;
        #pragma unroll
        for (int k16 = 0; k16 < 2; k16++) {
            uint32_t ko = (uint32_t)(k16 * 32);
            uint32_t aH[4][4], bH[2][4], bL[2][4];
            #pragma unroll
            for (int tm = 0; tm < 4; tm++)
                ldm_x4(aH[tm], st + 0*MATB + aAddr + (uint32_t)(tm*16*ROWP) + ko);
            #pragma unroll
            for (int p = 0; p < 2; p++) {
                ldm_x4(bH[p], st + 1*MATB + bAddr + (uint32_t)(p*16*ROWP) + ko);
                ldm_x4(bL[p], st + 2*MATB + bAddr + (uint32_t)(p*16*ROWP) + ko);
            }
            #pragma unroll
            for (int tm = 0; tm < 4; tm++) {
                #pragma unroll
                for (int tn = 0; tn < 4; tn++) {
                    int p = tn >> 1, h = (tn & 1) * 2;
                    mma16816(acc[tm][tn], aH[tm], bH[p][h], bH[p][h+1]);
                    mma16816(acc[tm][tn], aH[tm], bL[p][h], bL[p][h+1]);
                }
            }
        }
        __syncthreads();
    }

    // ---------------- epilogue: two 64-row halves staged through smem ----------------
    // sC: 64 rows x 136 floats = 34816 B <= 61440 B
    float* sC = (float*)smem;
    #pragma unroll
    for (int half = 0; half < 2; half++) {
        __syncthreads();
        if (wm == half) {
            #pragma unroll
            for (int tm = 0; tm < 4; tm++) {
                #pragma unroll
                for (int tn = 0; tn < 4; tn++) {
                    #pragma unroll
                    for (int r = 0; r < 4; r++) {
                        int row = tm*16 + (lane >> 2) + ((r >> 1) << 3);   // 0..63
                        int nn  = wn*32 + tn*8 + (lane & 3)*2 + (r & 1);
                        sC[row * 136 + nn] = acc[tm][tn][r];
                    }
                }
            }
        }
        __syncthreads();

        int rb = row0 + half * 64;
        if (MODE == 0) {
            #pragma unroll
            for (int j = 0; j < 8; j++) {
                int item = j * 256 + tid;
                int row = item >> 5, q = item & 31;
                float4 v  = *reinterpret_cast<float4*>(sC + row * 136 + q * 4);
                float4 bv = *reinterpret_cast<const float4*>(wob + n0 + q * 4);
                v.x += bv.x; v.y += bv.y; v.z += bv.z; v.w += bv.w;
                *reinterpret_cast<float4*>(Cout + (size_t)(rb + row) * NT + n0 + q * 4) = v;
            }
        } else {
            int c0g = n0 >> 2;
            #pragma unroll
            for (int j = 0; j < 8; j++) {
                int item = j * 256 + tid;
                int row = item >> 5, c = item & 31;
                int grow = rb + row;
                int cg = c0g + c;
                float4 g  = *reinterpret_cast<float4*>(sC + row * 136 + c * 4);
                float4 wv = *reinterpret_cast<const float4*>(wob + (size_t)grow * NT + n0 + c * 4);
                float gi = g.x + wv.x, gf = g.y + wv.y, go = g.z + wv.z, gc = g.w + wv.w;
                float ig = sigf(gi), fg = sigf(gf), og = sigf(go), ci = tanhf(gc);
                float sm = seq_mask[grow];
                float cp = first ? 0.f : cell[(size_t)grow * SD + cg];
                float tc = fg * cp + ig * ci;
                float th = og * tanhf(tc);
                float cv = tc * sm, hv = th * sm;
                cell[(size_t)grow * SD + cg] = cv;
                Cout[(size_t)grow * SD + cg] = hv;
                if (MODE == 2) {
                    finalH[(size_t)grow * SD + cg] = hv;
                    finalC[(size_t)grow * SD + cg] = cv;
                }
            }
        }
    }
}

// ---------------- launch ----------------
extern "C" void kernel_launch(void* const* d_in, const int* in_sizes, int n_in,
                              void* d_out, int out_size)
{
    const float* word     = (const float*)d_in[0];
    const float* sent     = (const float*)d_in[1];
    const float* seq_mask = (const float*)d_in[2];
    const float* in_mask  = (const float*)d_in[3];
    const float* out_mask = (const float*)d_in[4];
    const float* edge_emb = (const float*)d_in[5];
    const float* Wg_in    = (const float*)d_in[6];
    const float* Ug_in    = (const float*)d_in[7];
    const float* Wg_out   = (const float*)d_in[8];
    const float* Ug_out   = (const float*)d_in[9];
    const float* bvec     = (const float*)d_in[10];
    const int*   in_idx   = (const int*)d_in[11];
    const int*   in_edges = (const int*)d_in[12];
    const int*   out_idx  = (const int*)d_in[13];
    const int*   out_edges= (const int*)d_in[14];
    float* out = (float*)d_out;

    cudaFuncSetAttribute(mma_gemm<0>, cudaFuncAttributeMaxDynamicSharedMemorySize, SMEM_TOT);
    cudaFuncSetAttribute(mma_gemm<1>, cudaFuncAttributeMaxDynamicSharedMemorySize, SMEM_TOT);
    cudaFuncSetAttribute(mma_gemm<2>, cudaFuncAttributeMaxDynamicSharedMemorySize, SMEM_TOT);

    __half *p_irep,*p_orep,*p_iedS,*p_oedS,*p_hin,*p_hout;
    __half *p_Winh,*p_Winl,*p_Wouth,*p_Woutl,*p_Uinh,*p_Uinl,*p_Uouth,*p_Uoutl;
    float *p_bias,*p_wt,*p_cell;
    cudaGetSymbolAddress((void**)&p_irep,  g_irep);
    cudaGetSymbolAddress((void**)&p_orep,  g_orep);
    cudaGetSymbolAddress((void**)&p_iedS,  g_iedgeS);
    cudaGetSymbolAddress((void**)&p_oedS,  g_oedgeS);
    cudaGetSymbolAddress((void**)&p_hin,   g_hin);
    cudaGetSymbolAddress((void**)&p_hout,  g_hout);
    cudaGetSymbolAddress((void**)&p_Winh,  g_Win_hi);
    cudaGetSymbolAddress((void**)&p_Winl,  g_Win_lo);
    cudaGetSymbolAddress((void**)&p_Wouth, g_Wout_hi);
    cudaGetSymbolAddress((void**)&p_Woutl, g_Wout_lo);
    cudaGetSymbolAddress((void**)&p_Uinh,  g_Uin_hi);
    cudaGetSymbolAddress((void**)&p_Uinl,  g_Uin_lo);
    cudaGetSymbolAddress((void**)&p_Uouth, g_Uout_hi);
    cudaGetSymbolAddress((void**)&p_Uoutl, g_Uout_lo);
    cudaGetSymbolAddress((void**)&p_bias,  g_bias_i);
    cudaGetSymbolAddress((void**)&p_wt,    g_wterms);
    cudaGetSymbolAddress((void**)&p_cell,  g_cell);

    const size_t GS = (size_t)Mrows * SD;
    dim3 tb(32, 8);

    // 1) weight transpose + split
    conv_w_kernel<NK1,KP1><<<dim3(KP1/32, SD/32, 4), tb>>>(Wg_in,  p_Winh,  p_Winl);
    conv_w_kernel<NK1,KP1><<<dim3(KP1/32, SD/32, 4), tb>>>(Wg_out, p_Wouth, p_Woutl);
    conv_w_kernel<KP2,KP2><<<dim3(KP2/32, SD/32, 4), tb>>>(Ug_in,  p_Uinh,  p_Uinl);
    conv_w_kernel<KP2,KP2><<<dim3(KP2/32, SD/32, 4), tb>>>(Ug_out, p_Uouth, p_Uoutl);
    bias_kernel<<<NT/256, 256>>>(bvec);

    // 2) static neighbor sums
    prep_rep_kernel<<<Mrows, 128>>>(word, edge_emb, seq_mask,
                                    in_idx, in_edges, in_mask,
                                    out_idx, out_edges, out_mask);

    // 3) w_terms GEMM (incl. folded static edge terms of U-GEMMs)
    {
        SegList L;
        L.s[0] = { p_irep, p_Winh,        p_Winl,        KP1, KP1, KP1/32 };
        L.s[1] = { p_orep, p_Wouth,       p_Woutl,       KP1, KP1, KP1/32 };
        L.s[2] = { p_iedS, p_Uinh  + SD,  p_Uinl  + SD,  ED,  KP2, ED/32  };
        L.s[3] = { p_oedS, p_Uouth + SD,  p_Uoutl + SD,  ED,  KP2, ED/32  };
        L.nseg = 4;
        int NC = 2 * (KP1/32) + 2 * (ED/32);   // 28
        dim3 grid(Mrows/128, NT/128);
        mma_gemm<0><<<grid, 256, SMEM_TOT>>>(L, NC, p_bias, seq_mask,
                                             p_wt, nullptr, nullptr, nullptr, 0);
    }

    // 4) layers
    for (int l = 0; l < NLAYERS; l++) {
        const float* H = (l == 0) ? sent : (out + (size_t)(l-1)*GS);
        gather_h_kernel<<<Mrows, 128>>>(H, seq_mask, in_idx, in_mask, out_idx, out_mask);

        SegList L;
        L.s[0] = { p_hin,  p_Uinh,  p_Uinl,  SD, KP2, SD/32 };
        L.s[1] = { p_hout, p_Uouth, p_Uoutl, SD, KP2, SD/32 };
        L.s[2] = L.s[0]; L.s[3] = L.s[0];
        L.nseg = 2;
        int NC = 2 * (SD/32);   // 32
        dim3 grid(Mrows/128, NT/128);
        float* repL = out + (size_t)l*GS;
        if (l < NLAYERS-1) {
            mma_gemm<1><<<grid, 256, SMEM_TOT>>>(L, NC, p_wt, seq_mask,
                                                 repL, p_cell, nullptr, nullptr, (l == 0) ? 1 : 0);
        } else {
            mma_gemm<2><<<grid, 256, SMEM_TOT>>>(L, NC, p_wt, seq_mask,
                                                 repL, p_cell, out + 3*GS, out + 4*GS, 0);
        }
    }
}

// round 11
// speedup vs baseline: 1.2798x; 1.0157x over previous
#include <cuda_runtime.h>
#include <cuda_fp16.h>
#include <math.h>
#include <stdint.h>

// ---------------- static problem shape ----------------
#define Bb 16
#define Ss 512
#define Nn 16
#define WD 300
#define ED 64
#define SD 512
#define NK1 364           // WD+ED
#define KP1 384           // padded to 64
#define KP2 576           // SD+ED (Ug row count)
#define Mrows (Bb*Ss)     // 8192
#define NT 2048           // 4 gates * SD, interleaved n = c*4+g
#define NLAYERS 3

// ---------------- scratch (device globals; no allocations) ----------------
__device__ __align__(256) __half g_irep  [(size_t)Mrows*KP1];   // word+edge (no sm)
__device__ __align__(256) __half g_orep  [(size_t)Mrows*KP1];
__device__ __align__(256) __half g_iedgeS[(size_t)Mrows*ED];    // sm * edge_sum
__device__ __align__(256) __half g_oedgeS[(size_t)Mrows*ED];
__device__ __align__(256) __half g_hin   [(size_t)Mrows*SD];
__device__ __align__(256) __half g_hout  [(size_t)Mrows*SD];
__device__ __align__(256) __half g_Win_hi [(size_t)NT*KP1];
__device__ __align__(256) __half g_Win_lo [(size_t)NT*KP1];
__device__ __align__(256) __half g_Wout_hi[(size_t)NT*KP1];
__device__ __align__(256) __half g_Wout_lo[(size_t)NT*KP1];
__device__ __align__(256) __half g_Uin_hi [(size_t)NT*KP2];
__device__ __align__(256) __half g_Uin_lo [(size_t)NT*KP2];
__device__ __align__(256) __half g_Uout_hi[(size_t)NT*KP2];
__device__ __align__(256) __half g_Uout_lo[(size_t)NT*KP2];
__device__ __align__(256) float  g_bias_i[NT];
__device__ __align__(256) float  g_wterms[(size_t)Mrows*NT];
__device__ __align__(256) float  g_cell  [(size_t)Mrows*SD];

// ---------------- helpers ----------------
__device__ __forceinline__ uint32_t smem_u32(const void* p) {
    uint32_t a;
    asm("{ .reg .u64 t; cvta.to.shared.u64 t, %1; cvt.u32.u64 %0, t; }" : "=r"(a) : "l"(p));
    return a;
}
__device__ __forceinline__ void cpasync16(uint32_t dst, const void* src) {
    asm volatile("cp.async.ca.shared.global [%0], [%1], 16;" :: "r"(dst), "l"(src));
}
#define CP_COMMIT() asm volatile("cp.async.commit_group;" ::: "memory")
#define CP_WAIT(n)  asm volatile("cp.async.wait_group %0;" :: "n"(n) : "memory")

__device__ __forceinline__ void ldm_x4(uint32_t* r, uint32_t addr) {
    asm volatile("ldmatrix.sync.aligned.m8n8.x4.shared.b16 {%0,%1,%2,%3}, [%4];"
        : "=r"(r[0]), "=r"(r[1]), "=r"(r[2]), "=r"(r[3]) : "r"(addr));
}
__device__ __forceinline__ void mma16816(float* d, const uint32_t* a, uint32_t b0, uint32_t b1) {
    asm volatile("mma.sync.aligned.m16n8k16.row.col.f32.f16.f16.f32 "
        "{%0,%1,%2,%3}, {%4,%5,%6,%7}, {%8,%9}, {%0,%1,%2,%3};"
        : "+f"(d[0]), "+f"(d[1]), "+f"(d[2]), "+f"(d[3])
        : "r"(a[0]), "r"(a[1]), "r"(a[2]), "r"(a[3]), "r"(b0), "r"(b1));
}
__device__ __forceinline__ void split2h(float v, __half& hi, __half& lo) {
    hi = __float2half_rn(v);
    lo = __float2half_rn(v - __half2float(hi));
}
__device__ __forceinline__ float sigf(float x) { return 1.f / (1.f + __expf(-x)); }

// ---------------- weight transpose + split: W[g][k][c] -> Bt[(c*4+g)][k] fp16 hi/lo ----------------
template<int KSRC, int KPAD>
__global__ void conv_w_kernel(const float* __restrict__ W,
                              __half* __restrict__ dhi,
                              __half* __restrict__ dlo)
{
    __shared__ float t[32][33];
    int g = blockIdx.z, k0 = blockIdx.x * 32, c0 = blockIdx.y * 32;
    int tx = threadIdx.x, ty = threadIdx.y;   // 32 x 8
    #pragma unroll
    for (int i = 0; i < 4; i++) {
        int k = k0 + ty + i * 8;
        float v = (k < KSRC) ? W[((size_t)g * KSRC + k) * SD + c0 + tx] : 0.f;
        t[ty + i * 8][tx] = v;
    }
    __syncthreads();
    #pragma unroll
    for (int i = 0; i < 4; i++) {
        int c = ty + i * 8;
        int n = (c0 + c) * 4 + g;
        float v = t[tx][c];
        __half hi, lo; split2h(v, hi, lo);
        dhi[(size_t)n * KPAD + k0 + tx] = hi;
        dlo[(size_t)n * KPAD + k0 + tx] = lo;
    }
}

__global__ void bias_kernel(const float* __restrict__ b) {
    int n = blockIdx.x * 256 + threadIdx.x;
    if (n < NT) g_bias_i[n] = b[(n & 3) * SD + (n >> 2)];
}

// ---------------- static neighbor word+edge sums ----------------
__global__ void prep_rep_kernel(const float* __restrict__ word,
                                const float* __restrict__ edge_emb,
                                const float* __restrict__ seq_mask,
                                const int* __restrict__ in_idx,
                                const int* __restrict__ in_edges,
                                const float* __restrict__ in_mask,
                                const int* __restrict__ out_idx,
                                const int* __restrict__ out_edges,
                                const float* __restrict__ out_mask)
{
    int node = blockIdx.x;
    int b = node / Ss;
    float sm = seq_mask[node];
    __shared__ int   s_idx [2][Nn];
    __shared__ int   s_edge[2][Nn];
    __shared__ float s_msk [2][Nn];
    int tid = threadIdx.x;
    if (tid < Nn) {
        s_idx [0][tid] = in_idx  [(size_t)node*Nn + tid];
        s_edge[0][tid] = in_edges[(size_t)node*Nn + tid];
        s_msk [0][tid] = in_mask [(size_t)node*Nn + tid];
        s_idx [1][tid] = out_idx  [(size_t)node*Nn + tid];
        s_edge[1][tid] = out_edges[(size_t)node*Nn + tid];
        s_msk [1][tid] = out_mask [(size_t)node*Nn + tid];
    }
    __syncthreads();

    #pragma unroll
    for (int dir = 0; dir < 2; dir++) {
        __half* rep = dir ? g_orep : g_irep;
        __half* edS = dir ? g_oedgeS : g_iedgeS;
        for (int d = tid; d < WD; d += blockDim.x) {
            float acc = 0.f;
            #pragma unroll
            for (int n = 0; n < Nn; n++)
                acc += s_msk[dir][n] * word[((size_t)b*Ss + s_idx[dir][n])*WD + d];
            rep[(size_t)node*KP1 + d] = __float2half_rn(acc);
        }
        for (int d = tid; d < ED; d += blockDim.x) {
            float acc = 0.f;
            #pragma unroll
            for (int n = 0; n < Nn; n++)
                acc += s_msk[dir][n] * edge_emb[(size_t)s_edge[dir][n]*ED + d];
            rep[(size_t)node*KP1 + WD + d] = __float2half_rn(acc);
            edS[(size_t)node*ED + d] = __float2half_rn(acc * sm);
        }
        for (int d = NK1 + tid; d < KP1; d += blockDim.x)
            rep[(size_t)node*KP1 + d] = __float2half_rn(0.f);
    }
}

// ---------------- per-layer hidden gather (float4, single fp16 out) ----------------
__global__ void gather_h_kernel(const float* __restrict__ H,
                                const float* __restrict__ seq_mask,
                                const int* __restrict__ in_idx,
                                const float* __restrict__ in_mask,
                                const int* __restrict__ out_idx,
                                const float* __restrict__ out_mask)
{
    int node = blockIdx.x;
    int b = node / Ss;
    float sm = seq_mask[node];
    __shared__ int   s_idx[2][Nn];
    __shared__ float s_msk[2][Nn];
    int tid = threadIdx.x;   // 128 threads, each owns 4 dims
    if (tid < Nn) {
        s_idx[0][tid] = in_idx [(size_t)node*Nn + tid];
        s_msk[0][tid] = in_mask[(size_t)node*Nn + tid];
        s_idx[1][tid] = out_idx [(size_t)node*Nn + tid];
        s_msk[1][tid] = out_mask[(size_t)node*Nn + tid];
    }
    __syncthreads();

    const float4* Hb4 = reinterpret_cast<const float4*>(H + (size_t)b*Ss*SD);
    float4 ai = make_float4(0,0,0,0), ao = make_float4(0,0,0,0);
    #pragma unroll
    for (int n = 0; n < Nn; n++) {
        float m0 = s_msk[0][n];
        float4 v = Hb4[(size_t)s_idx[0][n]*(SD/4) + tid];
        ai.x += m0*v.x; ai.y += m0*v.y; ai.z += m0*v.z; ai.w += m0*v.w;
        float m1 = s_msk[1][n];
        float4 w = Hb4[(size_t)s_idx[1][n]*(SD/4) + tid];
        ao.x += m1*w.x; ao.y += m1*w.y; ao.z += m1*w.z; ao.w += m1*w.w;
    }
    __half2* pin  = reinterpret_cast<__half2*>(g_hin  + (size_t)node*SD) + tid*2;
    __half2* pout = reinterpret_cast<__half2*>(g_hout + (size_t)node*SD) + tid*2;
    pin[0]  = __floats2half2_rn(ai.x*sm, ai.y*sm);
    pin[1]  = __floats2half2_rn(ai.z*sm, ai.w*sm);
    pout[0] = __floats2half2_rn(ao.x*sm, ao.y*sm);
    pout[1] = __floats2half2_rn(ao.z*sm, ao.w*sm);
}

// ---------------- segmented fp16 2-product GEMM, tile 128x128, BK=64 ----------------
#define ROWP 144            // 128B data + 16B pad (16B aligned, conflict-free)
#define MATB 18432          // 128 rows * 144B
#define STAGEB (3*MATB)     // A, Bh, Bl = 55296
#define NSTAGE 2
#define SMEM_TOT (NSTAGE*STAGEB)   // 110592 -> 2 CTAs/SM (221KB <= 228KB)

struct Seg { const __half* A; const __half* Bh; const __half* Bl; int apitch, bpitch, nchunk; };
struct SegList { Seg s[4]; int nseg; };

__device__ __forceinline__ void chunk_src(const SegList& L, int idx, int row0, int n0,
    const __half*& A, const __half*& Bh, const __half*& Bl, int& ap, int& bp)
{
    #pragma unroll
    for (int s = 0; s < 4; s++) {
        if (s < L.nseg) {
            int n = L.s[s].nchunk;
            if (idx < n) {
                int k0 = idx * 64;
                ap = L.s[s].apitch; bp = L.s[s].bpitch;
                A  = L.s[s].A  + (size_t)row0 * ap + k0;
                Bh = L.s[s].Bh + (size_t)n0  * bp + k0;
                Bl = L.s[s].Bl + (size_t)n0  * bp + k0;
                return;
            }
            idx -= n;
        }
    }
}

__device__ __forceinline__ void load_chunk(uint32_t st,
    const __half* __restrict__ A, int ap,
    const __half* __restrict__ Bh, const __half* __restrict__ Bl, int bp, int tid)
{
    #pragma unroll
    for (int i = 0; i < 4; i++) {
        int idx = tid + i * 256;          // 0..1023: 128 rows x 8 segs of 16B
        int row = idx >> 3, seg = idx & 7;
        uint32_t doff = (uint32_t)(row * ROWP + seg * 16);
        cpasync16(st + 0*MATB + doff, (const char*)(A  + (size_t)row * ap) + seg * 16);
        cpasync16(st + 1*MATB + doff, (const char*)(Bh + (size_t)row * bp) + seg * 16);
        cpasync16(st + 2*MATB + doff, (const char*)(Bl + (size_t)row * bp) + seg * 16);
    }
}

// MODE 0: Cout[row][NT] = D + bias_i
// MODE 1: gates = D + w_terms -> LSTM -> Cout = h (SD layout), cell updated
// MODE 2: MODE 1 + finalH/finalC
template<int MODE>
__global__ __launch_bounds__(256, 2)
void mma_gemm(SegList L, int NC,
              const float* __restrict__ wob,
              const float* __restrict__ seq_mask,
              float* __restrict__ Cout,
              float* __restrict__ cell,
              float* __restrict__ finalH, float* __restrict__ finalC,
              int first)
{
    extern __shared__ char smem[];
    uint32_t sb = smem_u32(smem);
    int tid = threadIdx.x;
    int wid = tid >> 5, lane = tid & 31;
    int wm = wid >> 2, wn = wid & 3;       // warp 2x4: 64 rows x 32 cols
    int row0 = blockIdx.x * 128;
    int n0   = blockIdx.y * 128;

    float acc[4][4][4];
    #pragma unroll
    for (int a = 0; a < 4; a++)
        #pragma unroll
        for (int b = 0; b < 4; b++)
            #pragma unroll
            for (int c = 0; c < 4; c++) acc[a][b][c] = 0.f;

    uint32_t aAddr = (uint32_t)((wm * 64 + (lane & 15)) * ROWP + ((lane >> 4) << 4));
    uint32_t bRow  = (uint32_t)(wn * 32 + (lane & 7) + ((lane >> 4) << 3));
    uint32_t bAddr = bRow * ROWP + (((lane >> 3) & 1) << 4);

    // prologue: chunk 0 -> stage 0
    {
        const __half *A, *Bh, *Bl; int ap, bp;
        chunk_src(L, 0, row0, n0, A, Bh, Bl, ap, bp);
        load_chunk(sb, A, ap, Bh, Bl, bp, tid);
        CP_COMMIT();
    }

    for (int ci = 0; ci < NC; ci++) {
        if (ci + 1 < NC) {
            const __half *A, *Bh, *Bl; int ap, bp;
            chunk_src(L, ci + 1, row0, n0, A, Bh, Bl, ap, bp);
            load_chunk(sb + (uint32_t)((ci + 1) & 1) * STAGEB, A, ap, Bh, Bl, bp, tid);
        }
        CP_COMMIT();
        CP_WAIT(1);
        __syncthreads();

        uint32_t st = sb + (uint32_t)(ci & 1) * STAGEB;
        #pragma unroll
        for (int k16 = 0; k16 < 4; k16++) {
            uint32_t ko = (uint32_t)(k16 * 32);
            uint32_t aH[4][4], bH[2][4], bL[2][4];
            #pragma unroll
            for (int tm = 0; tm < 4; tm++)
                ldm_x4(aH[tm], st + 0*MATB + aAddr + (uint32_t)(tm*16*ROWP) + ko);
            #pragma unroll
            for (int p = 0; p < 2; p++) {
                ldm_x4(bH[p], st + 1*MATB + bAddr + (uint32_t)(p*16*ROWP) + ko);
                ldm_x4(bL[p], st + 2*MATB + bAddr + (uint32_t)(p*16*ROWP) + ko);
            }
            #pragma unroll
            for (int tm = 0; tm < 4; tm++) {
                #pragma unroll
                for (int tn = 0; tn < 4; tn++) {
                    int p = tn >> 1, h = (tn & 1) * 2;
                    mma16816(acc[tm][tn], aH[tm], bH[p][h], bH[p][h+1]);
                    mma16816(acc[tm][tn], aH[tm], bL[p][h], bL[p][h+1]);
                }
            }
        }
        __syncthreads();
    }

    // ---------------- epilogue: two 64-row halves staged through smem ----------------
    // sC: 64 rows x 136 floats = 34816 B <= SMEM_TOT
    float* sC = (float*)smem;
    #pragma unroll
    for (int half = 0; half < 2; half++) {
        __syncthreads();
        if (wm == half) {
            #pragma unroll
            for (int tm = 0; tm < 4; tm++) {
                #pragma unroll
                for (int tn = 0; tn < 4; tn++) {
                    #pragma unroll
                    for (int r = 0; r < 4; r++) {
                        int row = tm*16 + (lane >> 2) + ((r >> 1) << 3);   // 0..63
                        int nn  = wn*32 + tn*8 + (lane & 3)*2 + (r & 1);
                        sC[row * 136 + nn] = acc[tm][tn][r];
                    }
                }
            }
        }
        __syncthreads();

        int rb = row0 + half * 64;
        if (MODE == 0) {
            #pragma unroll
            for (int j = 0; j < 8; j++) {
                int item = j * 256 + tid;
                int row = item >> 5, q = item & 31;
                float4 v  = *reinterpret_cast<float4*>(sC + row * 136 + q * 4);
                float4 bv = *reinterpret_cast<const float4*>(wob + n0 + q * 4);
                v.x += bv.x; v.y += bv.y; v.z += bv.z; v.w += bv.w;
                *reinterpret_cast<float4*>(Cout + (size_t)(rb + row) * NT + n0 + q * 4) = v;
            }
        } else {
            int c0g = n0 >> 2;
            #pragma unroll
            for (int j = 0; j < 8; j++) {
                int item = j * 256 + tid;
                int row = item >> 5, c = item & 31;
                int grow = rb + row;
                int cg = c0g + c;
                float4 g  = *reinterpret_cast<float4*>(sC + row * 136 + c * 4);
                float4 wv = *reinterpret_cast<const float4*>(wob + (size_t)grow * NT + n0 + c * 4);
                float gi = g.x + wv.x, gf = g.y + wv.y, go = g.z + wv.z, gc = g.w + wv.w;
                float ig = sigf(gi), fg = sigf(gf), og = sigf(go), ci = tanhf(gc);
                float sm = seq_mask[grow];
                float cp = first ? 0.f : cell[(size_t)grow * SD + cg];
                float tc = fg * cp + ig * ci;
                float th = og * tanhf(tc);
                float cv = tc * sm, hv = th * sm;
                cell[(size_t)grow * SD + cg] = cv;
                Cout[(size_t)grow * SD + cg] = hv;
                if (MODE == 2) {
                    finalH[(size_t)grow * SD + cg] = hv;
                    finalC[(size_t)grow * SD + cg] = cv;
                }
            }
        }
    }
}

// ---------------- launch ----------------
extern "C" void kernel_launch(void* const* d_in, const int* in_sizes, int n_in,
                              void* d_out, int out_size)
{
    const float* word     = (const float*)d_in[0];
    const float* sent     = (const float*)d_in[1];
    const float* seq_mask = (const float*)d_in[2];
    const float* in_mask  = (const float*)d_in[3];
    const float* out_mask = (const float*)d_in[4];
    const float* edge_emb = (const float*)d_in[5];
    const float* Wg_in    = (const float*)d_in[6];
    const float* Ug_in    = (const float*)d_in[7];
    const float* Wg_out   = (const float*)d_in[8];
    const float* Ug_out   = (const float*)d_in[9];
    const float* bvec     = (const float*)d_in[10];
    const int*   in_idx   = (const int*)d_in[11];
    const int*   in_edges = (const int*)d_in[12];
    const int*   out_idx  = (const int*)d_in[13];
    const int*   out_edges= (const int*)d_in[14];
    float* out = (float*)d_out;

    cudaFuncSetAttribute(mma_gemm<0>, cudaFuncAttributeMaxDynamicSharedMemorySize, SMEM_TOT);
    cudaFuncSetAttribute(mma_gemm<1>, cudaFuncAttributeMaxDynamicSharedMemorySize, SMEM_TOT);
    cudaFuncSetAttribute(mma_gemm<2>, cudaFuncAttributeMaxDynamicSharedMemorySize, SMEM_TOT);

    __half *p_irep,*p_orep,*p_iedS,*p_oedS,*p_hin,*p_hout;
    __half *p_Winh,*p_Winl,*p_Wouth,*p_Woutl,*p_Uinh,*p_Uinl,*p_Uouth,*p_Uoutl;
    float *p_bias,*p_wt,*p_cell;
    cudaGetSymbolAddress((void**)&p_irep,  g_irep);
    cudaGetSymbolAddress((void**)&p_orep,  g_orep);
    cudaGetSymbolAddress((void**)&p_iedS,  g_iedgeS);
    cudaGetSymbolAddress((void**)&p_oedS,  g_oedgeS);
    cudaGetSymbolAddress((void**)&p_hin,   g_hin);
    cudaGetSymbolAddress((void**)&p_hout,  g_hout);
    cudaGetSymbolAddress((void**)&p_Winh,  g_Win_hi);
    cudaGetSymbolAddress((void**)&p_Winl,  g_Win_lo);
    cudaGetSymbolAddress((void**)&p_Wouth, g_Wout_hi);
    cudaGetSymbolAddress((void**)&p_Woutl, g_Wout_lo);
    cudaGetSymbolAddress((void**)&p_Uinh,  g_Uin_hi);
    cudaGetSymbolAddress((void**)&p_Uinl,  g_Uin_lo);
    cudaGetSymbolAddress((void**)&p_Uouth, g_Uout_hi);
    cudaGetSymbolAddress((void**)&p_Uoutl, g_Uout_lo);
    cudaGetSymbolAddress((void**)&p_bias,  g_bias_i);
    cudaGetSymbolAddress((void**)&p_wt,    g_wterms);
    cudaGetSymbolAddress((void**)&p_cell,  g_cell);

    const size_t GS = (size_t)Mrows * SD;
    dim3 tb(32, 8);

    // 1) weight transpose + split
    conv_w_kernel<NK1,KP1><<<dim3(KP1/32, SD/32, 4), tb>>>(Wg_in,  p_Winh,  p_Winl);
    conv_w_kernel<NK1,KP1><<<dim3(KP1/32, SD/32, 4), tb>>>(Wg_out, p_Wouth, p_Woutl);
    conv_w_kernel<KP2,KP2><<<dim3(KP2/32, SD/32, 4), tb>>>(Ug_in,  p_Uinh,  p_Uinl);
    conv_w_kernel<KP2,KP2><<<dim3(KP2/32, SD/32, 4), tb>>>(Ug_out, p_Uouth, p_Uoutl);
    bias_kernel<<<NT/256, 256>>>(bvec);

    // 2) static neighbor sums
    prep_rep_kernel<<<Mrows, 128>>>(word, edge_emb, seq_mask,
                                    in_idx, in_edges, in_mask,
                                    out_idx, out_edges, out_mask);

    // 3) w_terms GEMM (incl. folded static edge terms of U-GEMMs)
    {
        SegList L;
        L.s[0] = { p_irep, p_Winh,        p_Winl,        KP1, KP1, KP1/64 };
        L.s[1] = { p_orep, p_Wouth,       p_Woutl,       KP1, KP1, KP1/64 };
        L.s[2] = { p_iedS, p_Uinh  + SD,  p_Uinl  + SD,  ED,  KP2, ED/64  };
        L.s[3] = { p_oedS, p_Uouth + SD,  p_Uoutl + SD,  ED,  KP2, ED/64  };
        L.nseg = 4;
        int NC = 2 * (KP1/64) + 2 * (ED/64);   // 14
        dim3 grid(Mrows/128, NT/128);
        mma_gemm<0><<<grid, 256, SMEM_TOT>>>(L, NC, p_bias, seq_mask,
                                             p_wt, nullptr, nullptr, nullptr, 0);
    }

    // 4) layers
    for (int l = 0; l < NLAYERS; l++) {
        const float* H = (l == 0) ? sent : (out + (size_t)(l-1)*GS);
        gather_h_kernel<<<Mrows, 128>>>(H, seq_mask, in_idx, in_mask, out_idx, out_mask);

        SegList L;
        L.s[0] = { p_hin,  p_Uinh,  p_Uinl,  SD, KP2, SD/64 };
        L.s[1] = { p_hout, p_Uouth, p_Uoutl, SD, KP2, SD/64 };
        L.s[2] = L.s[0]; L.s[3] = L.s[0];
        L.nseg = 2;
        int NC = 2 * (SD/64);   // 16
        dim3 grid(Mrows/128, NT/128);
        float* repL = out + (size_t)l*GS;
        if (l < NLAYERS-1) {
            mma_gemm<1><<<grid, 256, SMEM_TOT>>>(L, NC, p_wt, seq_mask,
                                                 repL, p_cell, nullptr, nullptr, (l == 0) ? 1 : 0);
        } else {
            mma_gemm<2><<<grid, 256, SMEM_TOT>>>(L, NC, p_wt, seq_mask,
                                                 repL, p_cell, out + 3*GS, out + 4*GS, 0);
        }
    }
}

// round 12
// speedup vs baseline: 1.2881x; 1.0065x over previous
#include <cuda_runtime.h>
#include <cuda_fp16.h>
#include <math.h>
#include <stdint.h>

// ---------------- static problem shape ----------------
#define Bb 16
#define Ss 512
#define Nn 16
#define WD 300
#define ED 64
#define SD 512
#define NK1 364           // WD+ED
#define KP1 384           // padded to 64
#define KP2 576           // SD+ED (Ug row count)
#define Mrows (Bb*Ss)     // 8192
#define NT 2048           // 4 gates * SD, interleaved n = c*4+g
#define NLAYERS 3

// ---------------- scratch (device globals; no allocations) ----------------
__device__ __align__(256) __half g_irep  [(size_t)Mrows*KP1];   // word+edge (no sm)
__device__ __align__(256) __half g_orep  [(size_t)Mrows*KP1];
__device__ __align__(256) __half g_iedgeS[(size_t)Mrows*ED];    // sm * edge_sum
__device__ __align__(256) __half g_oedgeS[(size_t)Mrows*ED];
__device__ __align__(256) __half g_hin   [(size_t)Mrows*SD];
__device__ __align__(256) __half g_hout  [(size_t)Mrows*SD];
__device__ __align__(256) __half g_hH    [(size_t)Mrows*SD];    // fp16 mirror of hidden state
__device__ __align__(256) __half g_Win_hi [(size_t)NT*KP1];
__device__ __align__(256) __half g_Win_lo [(size_t)NT*KP1];
__device__ __align__(256) __half g_Wout_hi[(size_t)NT*KP1];
__device__ __align__(256) __half g_Wout_lo[(size_t)NT*KP1];
__device__ __align__(256) __half g_Uin_hi [(size_t)NT*KP2];
__device__ __align__(256) __half g_Uin_lo [(size_t)NT*KP2];
__device__ __align__(256) __half g_Uout_hi[(size_t)NT*KP2];
__device__ __align__(256) __half g_Uout_lo[(size_t)NT*KP2];
__device__ __align__(256) float  g_bias_i[NT];
__device__ __align__(256) float  g_wterms[(size_t)Mrows*NT];
__device__ __align__(256) float  g_cell  [(size_t)Mrows*SD];

// ---------------- helpers ----------------
__device__ __forceinline__ uint32_t smem_u32(const void* p) {
    uint32_t a;
    asm("{ .reg .u64 t; cvta.to.shared.u64 t, %1; cvt.u32.u64 %0, t; }" : "=r"(a) : "l"(p));
    return a;
}
__device__ __forceinline__ void cpasync16(uint32_t dst, const void* src) {
    asm volatile("cp.async.ca.shared.global [%0], [%1], 16;" :: "r"(dst), "l"(src));
}
#define CP_COMMIT() asm volatile("cp.async.commit_group;" ::: "memory")
#define CP_WAIT(n)  asm volatile("cp.async.wait_group %0;" :: "n"(n) : "memory")

__device__ __forceinline__ void ldm_x4(uint32_t* r, uint32_t addr) {
    asm volatile("ldmatrix.sync.aligned.m8n8.x4.shared.b16 {%0,%1,%2,%3}, [%4];"
        : "=r"(r[0]), "=r"(r[1]), "=r"(r[2]), "=r"(r[3]) : "r"(addr));
}
__device__ __forceinline__ void mma16816(float* d, const uint32_t* a, uint32_t b0, uint32_t b1) {
    asm volatile("mma.sync.aligned.m16n8k16.row.col.f32.f16.f16.f32 "
        "{%0,%1,%2,%3}, {%4,%5,%6,%7}, {%8,%9}, {%0,%1,%2,%3};"
        : "+f"(d[0]), "+f"(d[1]), "+f"(d[2]), "+f"(d[3])
        : "r"(a[0]), "r"(a[1]), "r"(a[2]), "r"(a[3]), "r"(b0), "r"(b1));
}
__device__ __forceinline__ void split2h(float v, __half& hi, __half& lo) {
    hi = __float2half_rn(v);
    lo = __float2half_rn(v - __half2float(hi));
}
__device__ __forceinline__ float sigf(float x) { return 1.f / (1.f + __expf(-x)); }

// ---------------- weight transpose + split: W[g][k][c] -> Bt[(c*4+g)][k] fp16 hi/lo ----------------
template<int KSRC, int KPAD>
__global__ void conv_w_kernel(const float* __restrict__ W,
                              __half* __restrict__ dhi,
                              __half* __restrict__ dlo)
{
    __shared__ float t[32][33];
    int g = blockIdx.z, k0 = blockIdx.x * 32, c0 = blockIdx.y * 32;
    int tx = threadIdx.x, ty = threadIdx.y;   // 32 x 8
    #pragma unroll
    for (int i = 0; i < 4; i++) {
        int k = k0 + ty + i * 8;
        float v = (k < KSRC) ? W[((size_t)g * KSRC + k) * SD + c0 + tx] : 0.f;
        t[ty + i * 8][tx] = v;
    }
    __syncthreads();
    #pragma unroll
    for (int i = 0; i < 4; i++) {
        int c = ty + i * 8;
        int n = (c0 + c) * 4 + g;
        float v = t[tx][c];
        __half hi, lo; split2h(v, hi, lo);
        dhi[(size_t)n * KPAD + k0 + tx] = hi;
        dlo[(size_t)n * KPAD + k0 + tx] = lo;
    }
}

__global__ void bias_kernel(const float* __restrict__ b) {
    int n = blockIdx.x * 256 + threadIdx.x;
    if (n < NT) g_bias_i[n] = b[(n & 3) * SD + (n >> 2)];
}

// ---------------- sentence_repres fp32 -> fp16 mirror ----------------
__global__ void h2h_kernel(const float* __restrict__ src) {
    size_t i = (size_t)blockIdx.x * 256 + threadIdx.x;   // half2 index
    float2 v = reinterpret_cast<const float2*>(src)[i];
    reinterpret_cast<__half2*>(g_hH)[i] = __floats2half2_rn(v.x, v.y);
}

// ---------------- static neighbor word+edge sums ----------------
__global__ void prep_rep_kernel(const float* __restrict__ word,
                                const float* __restrict__ edge_emb,
                                const float* __restrict__ seq_mask,
                                const int* __restrict__ in_idx,
                                const int* __restrict__ in_edges,
                                const float* __restrict__ in_mask,
                                const int* __restrict__ out_idx,
                                const int* __restrict__ out_edges,
                                const float* __restrict__ out_mask)
{
    int node = blockIdx.x;
    int b = node / Ss;
    float sm = seq_mask[node];
    __shared__ int   s_idx [2][Nn];
    __shared__ int   s_edge[2][Nn];
    __shared__ float s_msk [2][Nn];
    int tid = threadIdx.x;
    if (tid < Nn) {
        s_idx [0][tid] = in_idx  [(size_t)node*Nn + tid];
        s_edge[0][tid] = in_edges[(size_t)node*Nn + tid];
        s_msk [0][tid] = in_mask [(size_t)node*Nn + tid];
        s_idx [1][tid] = out_idx  [(size_t)node*Nn + tid];
        s_edge[1][tid] = out_edges[(size_t)node*Nn + tid];
        s_msk [1][tid] = out_mask [(size_t)node*Nn + tid];
    }
    __syncthreads();

    #pragma unroll
    for (int dir = 0; dir < 2; dir++) {
        __half* rep = dir ? g_orep : g_irep;
        __half* edS = dir ? g_oedgeS : g_iedgeS;
        for (int d = tid; d < WD; d += blockDim.x) {
            float acc = 0.f;
            #pragma unroll
            for (int n = 0; n < Nn; n++)
                acc += s_msk[dir][n] * word[((size_t)b*Ss + s_idx[dir][n])*WD + d];
            rep[(size_t)node*KP1 + d] = __float2half_rn(acc);
        }
        for (int d = tid; d < ED; d += blockDim.x) {
            float acc = 0.f;
            #pragma unroll
            for (int n = 0; n < Nn; n++)
                acc += s_msk[dir][n] * edge_emb[(size_t)s_edge[dir][n]*ED + d];
            rep[(size_t)node*KP1 + WD + d] = __float2half_rn(acc);
            edS[(size_t)node*ED + d] = __float2half_rn(acc * sm);
        }
        for (int d = NK1 + tid; d < KP1; d += blockDim.x)
            rep[(size_t)node*KP1 + d] = __float2half_rn(0.f);
    }
}

// ---------------- per-layer hidden gather: reads fp16 mirror g_hH ----------------
__global__ void gather_h_kernel(const float* __restrict__ seq_mask,
                                const int* __restrict__ in_idx,
                                const float* __restrict__ in_mask,
                                const int* __restrict__ out_idx,
                                const float* __restrict__ out_mask)
{
    int node = blockIdx.x;
    int b = node / Ss;
    float sm = seq_mask[node];
    __shared__ int   s_idx[2][Nn];
    __shared__ float s_msk[2][Nn];
    int tid = threadIdx.x;   // 128 threads, each owns 4 dims
    if (tid < Nn) {
        s_idx[0][tid] = in_idx [(size_t)node*Nn + tid];
        s_msk[0][tid] = in_mask[(size_t)node*Nn + tid];
        s_idx[1][tid] = out_idx [(size_t)node*Nn + tid];
        s_msk[1][tid] = out_mask[(size_t)node*Nn + tid];
    }
    __syncthreads();

    const __half* Hb = g_hH + (size_t)b*Ss*SD;
    float4 ai = make_float4(0,0,0,0), ao = make_float4(0,0,0,0);
    #pragma unroll
    for (int n = 0; n < Nn; n++) {
        float m0 = s_msk[0][n];
        uint2 u = reinterpret_cast<const uint2*>(Hb + (size_t)s_idx[0][n]*SD)[tid];
        float2 f0 = __half22float2(*reinterpret_cast<__half2*>(&u.x));
        float2 f1 = __half22float2(*reinterpret_cast<__half2*>(&u.y));
        ai.x += m0*f0.x; ai.y += m0*f0.y; ai.z += m0*f1.x; ai.w += m0*f1.y;
        float m1 = s_msk[1][n];
        uint2 w = reinterpret_cast<const uint2*>(Hb + (size_t)s_idx[1][n]*SD)[tid];
        float2 g0 = __half22float2(*reinterpret_cast<__half2*>(&w.x));
        float2 g1 = __half22float2(*reinterpret_cast<__half2*>(&w.y));
        ao.x += m1*g0.x; ao.y += m1*g0.y; ao.z += m1*g1.x; ao.w += m1*g1.y;
    }
    __half2* pin  = reinterpret_cast<__half2*>(g_hin  + (size_t)node*SD) + tid*2;
    __half2* pout = reinterpret_cast<__half2*>(g_hout + (size_t)node*SD) + tid*2;
    pin[0]  = __floats2half2_rn(ai.x*sm, ai.y*sm);
    pin[1]  = __floats2half2_rn(ai.z*sm, ai.w*sm);
    pout[0] = __floats2half2_rn(ao.x*sm, ao.y*sm);
    pout[1] = __floats2half2_rn(ao.z*sm, ao.w*sm);
}

// ---------------- segmented fp16 2-product GEMM, tile 128x128, BK=64 ----------------
#define ROWP 144            // 128B data + 16B pad (16B aligned, conflict-free)
#define MATB 18432          // 128 rows * 144B
#define STAGEB (3*MATB)     // A, Bh, Bl = 55296
#define NSTAGE 2
#define SMEM_TOT (NSTAGE*STAGEB)   // 110592 -> 2 CTAs/SM (221KB <= 228KB)

struct Seg { const __half* A; const __half* Bh; const __half* Bl; int apitch, bpitch, nchunk; };
struct SegList { Seg s[4]; int nseg; };

__device__ __forceinline__ void chunk_src(const SegList& L, int idx, int row0, int n0,
    const __half*& A, const __half*& Bh, const __half*& Bl, int& ap, int& bp)
{
    #pragma unroll
    for (int s = 0; s < 4; s++) {
        if (s < L.nseg) {
            int n = L.s[s].nchunk;
            if (idx < n) {
                int k0 = idx * 64;
                ap = L.s[s].apitch; bp = L.s[s].bpitch;
                A  = L.s[s].A  + (size_t)row0 * ap + k0;
                Bh = L.s[s].Bh + (size_t)n0  * bp + k0;
                Bl = L.s[s].Bl + (size_t)n0  * bp + k0;
                return;
            }
            idx -= n;
        }
    }
}

__device__ __forceinline__ void load_chunk(uint32_t st,
    const __half* __restrict__ A, int ap,
    const __half* __restrict__ Bh, const __half* __restrict__ Bl, int bp, int tid)
{
    #pragma unroll
    for (int i = 0; i < 4; i++) {
        int idx = tid + i * 256;          // 0..1023: 128 rows x 8 segs of 16B
        int row = idx >> 3, seg = idx & 7;
        uint32_t doff = (uint32_t)(row * ROWP + seg * 16);
        cpasync16(st + 0*MATB + doff, (const char*)(A  + (size_t)row * ap) + seg * 16);
        cpasync16(st + 1*MATB + doff, (const char*)(Bh + (size_t)row * bp) + seg * 16);
        cpasync16(st + 2*MATB + doff, (const char*)(Bl + (size_t)row * bp) + seg * 16);
    }
}

// MODE 0: Cout[row][NT] = D + bias_i
// MODE 1: gates = D + w_terms -> LSTM -> Cout = h (SD layout), cell updated, g_hH mirrored
// MODE 2: MODE 1 + finalH/finalC
template<int MODE>
__global__ __launch_bounds__(256, 2)
void mma_gemm(SegList L, int NC,
              const float* __restrict__ wob,
              const float* __restrict__ seq_mask,
              float* __restrict__ Cout,
              float* __restrict__ cell,
              float* __restrict__ finalH, float* __restrict__ finalC,
              int first)
{
    extern __shared__ char smem[];
    uint32_t sb = smem_u32(smem);
    int tid = threadIdx.x;
    int wid = tid >> 5, lane = tid & 31;
    int wm = wid >> 2, wn = wid & 3;       // warp 2x4: 64 rows x 32 cols
    int row0 = blockIdx.x * 128;
    int n0   = blockIdx.y * 128;

    float acc[4][4][4];
    #pragma unroll
    for (int a = 0; a < 4; a++)
        #pragma unroll
        for (int b = 0; b < 4; b++)
            #pragma unroll
            for (int c = 0; c < 4; c++) acc[a][b][c] = 0.f;

    uint32_t aAddr = (uint32_t)((wm * 64 + (lane & 15)) * ROWP + ((lane >> 4) << 4));
    uint32_t bRow  = (uint32_t)(wn * 32 + (lane & 7) + ((lane >> 4) << 3));
    uint32_t bAddr = bRow * ROWP + (((lane >> 3) & 1) << 4);

    // prologue: chunk 0 -> stage 0
    {
        const __half *A, *Bh, *Bl; int ap, bp;
        chunk_src(L, 0, row0, n0, A, Bh, Bl, ap, bp);
        load_chunk(sb, A, ap, Bh, Bl, bp, tid);
        CP_COMMIT();
    }

    for (int ci = 0; ci < NC; ci++) {
        if (ci + 1 < NC) {
            const __half *A, *Bh, *Bl; int ap, bp;
            chunk_src(L, ci + 1, row0, n0, A, Bh, Bl, ap, bp);
            load_chunk(sb + (uint32_t)((ci + 1) & 1) * STAGEB, A, ap, Bh, Bl, bp, tid);
        }
        CP_COMMIT();
        CP_WAIT(1);
        __syncthreads();

        uint32_t st = sb + (uint32_t)(ci & 1) * STAGEB;
        #pragma unroll
        for (int k16 = 0; k16 < 4; k16++) {
            uint32_t ko = (uint32_t)(k16 * 32);
            uint32_t aH[4][4], bH[2][4], bL[2][4];
            #pragma unroll
            for (int tm = 0; tm < 4; tm++)
                ldm_x4(aH[tm], st + 0*MATB + aAddr + (uint32_t)(tm*16*ROWP) + ko);
            #pragma unroll
            for (int p = 0; p < 2; p++) {
                ldm_x4(bH[p], st + 1*MATB + bAddr + (uint32_t)(p*16*ROWP) + ko);
                ldm_x4(bL[p], st + 2*MATB + bAddr + (uint32_t)(p*16*ROWP) + ko);
            }
            #pragma unroll
            for (int tm = 0; tm < 4; tm++) {
                #pragma unroll
                for (int tn = 0; tn < 4; tn++) {
                    int p = tn >> 1, h = (tn & 1) * 2;
                    mma16816(acc[tm][tn], aH[tm], bH[p][h], bH[p][h+1]);
                    mma16816(acc[tm][tn], aH[tm], bL[p][h], bL[p][h+1]);
                }
            }
        }
        __syncthreads();
    }

    // ---------------- epilogue: two 64-row halves staged through smem ----------------
    // sC: 64 rows x 136 floats = 34816 B <= SMEM_TOT
    float* sC = (float*)smem;
    #pragma unroll
    for (int half = 0; half < 2; half++) {
        __syncthreads();
        if (wm == half) {
            #pragma unroll
            for (int tm = 0; tm < 4; tm++) {
                #pragma unroll
                for (int tn = 0; tn < 4; tn++) {
                    #pragma unroll
                    for (int r = 0; r < 4; r++) {
                        int row = tm*16 + (lane >> 2) + ((r >> 1) << 3);   // 0..63
                        int nn  = wn*32 + tn*8 + (lane & 3)*2 + (r & 1);
                        sC[row * 136 + nn] = acc[tm][tn][r];
                    }
                }
            }
        }
        __syncthreads();

        int rb = row0 + half * 64;
        if (MODE == 0) {
            #pragma unroll
            for (int j = 0; j < 8; j++) {
                int item = j * 256 + tid;
                int row = item >> 5, q = item & 31;
                float4 v  = *reinterpret_cast<float4*>(sC + row * 136 + q * 4);
                float4 bv = *reinterpret_cast<const float4*>(wob + n0 + q * 4);
                v.x += bv.x; v.y += bv.y; v.z += bv.z; v.w += bv.w;
                *reinterpret_cast<float4*>(Cout + (size_t)(rb + row) * NT + n0 + q * 4) = v;
            }
        } else {
            int c0g = n0 >> 2;
            #pragma unroll
            for (int j = 0; j < 8; j++) {
                int item = j * 256 + tid;
                int row = item >> 5, c = item & 31;
                int grow = rb + row;
                int cg = c0g + c;
                float4 g  = *reinterpret_cast<float4*>(sC + row * 136 + c * 4);
                float4 wv = *reinterpret_cast<const float4*>(wob + (size_t)grow * NT + n0 + c * 4);
                float gi = g.x + wv.x, gf = g.y + wv.y, go = g.z + wv.z, gc = g.w + wv.w;
                float ig = sigf(gi), fg = sigf(gf), og = sigf(go), ci = tanhf(gc);
                float sm = seq_mask[grow];
                float cp = first ? 0.f : cell[(size_t)grow * SD + cg];
                float tc = fg * cp + ig * ci;
                float th = og * tanhf(tc);
                float cv = tc * sm, hv = th * sm;
                cell[(size_t)grow * SD + cg] = cv;
                Cout[(size_t)grow * SD + cg] = hv;
                g_hH[(size_t)grow * SD + cg] = __float2half_rn(hv);
                if (MODE == 2) {
                    finalH[(size_t)grow * SD + cg] = hv;
                    finalC[(size_t)grow * SD + cg] = cv;
                }
            }
        }
    }
}

// ---------------- launch ----------------
extern "C" void kernel_launch(void* const* d_in, const int* in_sizes, int n_in,
                              void* d_out, int out_size)
{
    const float* word     = (const float*)d_in[0];
    const float* sent     = (const float*)d_in[1];
    const float* seq_mask = (const float*)d_in[2];
    const float* in_mask  = (const float*)d_in[3];
    const float* out_mask = (const float*)d_in[4];
    const float* edge_emb = (const float*)d_in[5];
    const float* Wg_in    = (const float*)d_in[6];
    const float* Ug_in    = (const float*)d_in[7];
    const float* Wg_out   = (const float*)d_in[8];
    const float* Ug_out   = (const float*)d_in[9];
    const float* bvec     = (const float*)d_in[10];
    const int*   in_idx   = (const int*)d_in[11];
    const int*   in_edges = (const int*)d_in[12];
    const int*   out_idx  = (const int*)d_in[13];
    const int*   out_edges= (const int*)d_in[14];
    float* out = (float*)d_out;

    cudaFuncSetAttribute(mma_gemm<0>, cudaFuncAttributeMaxDynamicSharedMemorySize, SMEM_TOT);
    cudaFuncSetAttribute(mma_gemm<1>, cudaFuncAttributeMaxDynamicSharedMemorySize, SMEM_TOT);
    cudaFuncSetAttribute(mma_gemm<2>, cudaFuncAttributeMaxDynamicSharedMemorySize, SMEM_TOT);

    __half *p_irep,*p_orep,*p_iedS,*p_oedS,*p_hin,*p_hout;
    __half *p_Winh,*p_Winl,*p_Wouth,*p_Woutl,*p_Uinh,*p_Uinl,*p_Uouth,*p_Uoutl;
    float *p_bias,*p_wt,*p_cell;
    cudaGetSymbolAddress((void**)&p_irep,  g_irep);
    cudaGetSymbolAddress((void**)&p_orep,  g_orep);
    cudaGetSymbolAddress((void**)&p_iedS,  g_iedgeS);
    cudaGetSymbolAddress((void**)&p_oedS,  g_oedgeS);
    cudaGetSymbolAddress((void**)&p_hin,   g_hin);
    cudaGetSymbolAddress((void**)&p_hout,  g_hout);
    cudaGetSymbolAddress((void**)&p_Winh,  g_Win_hi);
    cudaGetSymbolAddress((void**)&p_Winl,  g_Win_lo);
    cudaGetSymbolAddress((void**)&p_Wouth, g_Wout_hi);
    cudaGetSymbolAddress((void**)&p_Woutl, g_Wout_lo);
    cudaGetSymbolAddress((void**)&p_Uinh,  g_Uin_hi);
    cudaGetSymbolAddress((void**)&p_Uinl,  g_Uin_lo);
    cudaGetSymbolAddress((void**)&p_Uouth, g_Uout_hi);
    cudaGetSymbolAddress((void**)&p_Uoutl, g_Uout_lo);
    cudaGetSymbolAddress((void**)&p_bias,  g_bias_i);
    cudaGetSymbolAddress((void**)&p_wt,    g_wterms);
    cudaGetSymbolAddress((void**)&p_cell,  g_cell);

    const size_t GS = (size_t)Mrows * SD;
    dim3 tb(32, 8);

    // 1) weight transpose + split
    conv_w_kernel<NK1,KP1><<<dim3(KP1/32, SD/32, 4), tb>>>(Wg_in,  p_Winh,  p_Winl);
    conv_w_kernel<NK1,KP1><<<dim3(KP1/32, SD/32, 4), tb>>>(Wg_out, p_Wouth, p_Woutl);
    conv_w_kernel<KP2,KP2><<<dim3(KP2/32, SD/32, 4), tb>>>(Ug_in,  p_Uinh,  p_Uinl);
    conv_w_kernel<KP2,KP2><<<dim3(KP2/32, SD/32, 4), tb>>>(Ug_out, p_Uouth, p_Uoutl);
    bias_kernel<<<NT/256, 256>>>(bvec);

    // 2) static neighbor sums + fp16 mirror of sentence_repres
    prep_rep_kernel<<<Mrows, 128>>>(word, edge_emb, seq_mask,
                                    in_idx, in_edges, in_mask,
                                    out_idx, out_edges, out_mask);
    h2h_kernel<<<(unsigned)(GS/2/256), 256>>>(sent);

    // 3) w_terms GEMM (incl. folded static edge terms of U-GEMMs)
    {
        SegList L;
        L.s[0] = { p_irep, p_Winh,        p_Winl,        KP1, KP1, KP1/64 };
        L.s[1] = { p_orep, p_Wouth,       p_Woutl,       KP1, KP1, KP1/64 };
        L.s[2] = { p_iedS, p_Uinh  + SD,  p_Uinl  + SD,  ED,  KP2, ED/64  };
        L.s[3] = { p_oedS, p_Uouth + SD,  p_Uoutl + SD,  ED,  KP2, ED/64  };
        L.nseg = 4;
        int NC = 2 * (KP1/64) + 2 * (ED/64);   // 14
        dim3 grid(Mrows/128, NT/128);
        mma_gemm<0><<<grid, 256, SMEM_TOT>>>(L, NC, p_bias, seq_mask,
                                             p_wt, nullptr, nullptr, nullptr, 0);
    }

    // 4) layers
    for (int l = 0; l < NLAYERS; l++) {
        gather_h_kernel<<<Mrows, 128>>>(seq_mask, in_idx, in_mask, out_idx, out_mask);

        SegList L;
        L.s[0] = { p_hin,  p_Uinh,  p_Uinl,  SD, KP2, SD/64 };
        L.s[1] = { p_hout, p_Uouth, p_Uoutl, SD, KP2, SD/64 };
        L.s[2] = L.s[0]; L.s[3] = L.s[0];
        L.nseg = 2;
        int NC = 2 * (SD/64);   // 16
        dim3 grid(Mrows/128, NT/128);
        float* repL = out + (size_t)l*GS;
        if (l < NLAYERS-1) {
            mma_gemm<1><<<grid, 256, SMEM_TOT>>>(L, NC, p_wt, seq_mask,
                                                 repL, p_cell, nullptr, nullptr, (l == 0) ? 1 : 0);
        } else {
            mma_gemm<2><<<grid, 256, SMEM_TOT>>>(L, NC, p_wt, seq_mask,
                                                 repL, p_cell, out + 3*GS, out + 4*GS, 0);
        }
    }
}